// round 2
// baseline (speedup 1.0000x reference)
#include <cuda_runtime.h>
#include <cuda_bf16.h>
#include <cstdint>

#define NROWS 16384
#define KDIM  4096
#define ODIM  4096

#define BM 128
#define BN 128
#define BK 64
#define LDSH (BK + 8)   // padded smem stride in bf16 elems (144B rows -> conflict-free ldmatrix)

// ---------------- scratch (static device globals; no allocation allowed) ----------------
__device__ __nv_bfloat16 g_qx[(size_t)NROWS * KDIM];   // 128 MB
__device__ __nv_bfloat16 g_qw[(size_t)ODIM * KDIM];    // 32 MB
__device__ float g_wscale[ODIM];
__device__ unsigned int g_xmax_u, g_xmin_u, g_rmax_u, g_rmin_u;
__device__ float g_sc, g_zp, g_resc, g_rezp;

// ---------------- helpers ----------------
__global__ void init_kernel() {
    g_xmax_u = 0u; g_xmin_u = 0u; g_rmax_u = 0u; g_rmin_u = 0u;
}

// monotone-uint min/max atomics:
//  max side: values >= 0, float bits are monotone as unsigned
//  min side: values <= 0, more negative -> larger unsigned bits
__device__ __forceinline__ void block_minmax_atomic(float tmn, float tmx,
                                                    unsigned int* gmin, unsigned int* gmax) {
    #pragma unroll
    for (int o = 16; o > 0; o >>= 1) {
        tmx = fmaxf(tmx, __shfl_xor_sync(0xffffffffu, tmx, o));
        tmn = fminf(tmn, __shfl_xor_sync(0xffffffffu, tmn, o));
    }
    __shared__ float smx[32], smn[32];
    int w = threadIdx.x >> 5, nw = blockDim.x >> 5;
    if ((threadIdx.x & 31) == 0) { smx[w] = tmx; smn[w] = tmn; }
    __syncthreads();
    if (threadIdx.x == 0) {
        for (int i = 1; i < nw; i++) { tmx = fmaxf(tmx, smx[i]); tmn = fminf(tmn, smn[i]); }
        atomicMax(gmax, __float_as_uint(fmaxf(tmx, 0.f)));
        atomicMax(gmin, __float_as_uint(fminf(tmn, 0.f)));
    }
}

// ---------------- pass 1: global min/max of x ----------------
__global__ void minmax_x_kernel(const float4* __restrict__ x4, int n4) {
    float tmx = 0.f, tmn = 0.f;
    for (int i = blockIdx.x * blockDim.x + threadIdx.x; i < n4; i += gridDim.x * blockDim.x) {
        float4 v = x4[i];
        tmx = fmaxf(tmx, fmaxf(fmaxf(v.x, v.y), fmaxf(v.z, v.w)));
        tmn = fminf(tmn, fminf(fminf(v.x, v.y), fminf(v.z, v.w)));
    }
    block_minmax_atomic(tmn, tmx, &g_xmin_u, &g_xmax_u);
}

__global__ void params1_kernel() {
    float mx = __uint_as_float(g_xmax_u);     // already >= 0
    float mn = __uint_as_float(g_xmin_u);     // already <= 0
    float sc = (mx - mn) / 255.f;
    g_sc = sc;
    g_zp = rintf(-128.f - mn / sc);
}

// ---------------- weight quant: per-row symmetric ----------------
__global__ void quantw_kernel(const float* __restrict__ w) {
    int row = blockIdx.x;
    const float4* wr = (const float4*)(w + (size_t)row * KDIM);
    float4 v[4];
    float am = 0.f;
    #pragma unroll
    for (int i = 0; i < 4; i++) {
        v[i] = wr[threadIdx.x + i * 256];
        am = fmaxf(am, fmaxf(fmaxf(fabsf(v[i].x), fabsf(v[i].y)),
                             fmaxf(fabsf(v[i].z), fabsf(v[i].w))));
    }
    #pragma unroll
    for (int o = 16; o > 0; o >>= 1) am = fmaxf(am, __shfl_xor_sync(0xffffffffu, am, o));
    __shared__ float sred[8];
    __shared__ float swsv;
    if ((threadIdx.x & 31) == 0) sred[threadIdx.x >> 5] = am;
    __syncthreads();
    if (threadIdx.x == 0) {
        for (int i = 1; i < 8; i++) am = fmaxf(am, sred[i]);
        float ws = am / 127.f;
        swsv = ws;
        g_wscale[row] = ws;
    }
    __syncthreads();
    float ws = swsv;
    __nv_bfloat16* qrow = g_qw + (size_t)row * KDIM;
    #pragma unroll
    for (int i = 0; i < 4; i++) {
        int c = (threadIdx.x + i * 256) * 4;
        float q0 = fminf(fmaxf(rintf(v[i].x / ws), -127.f), 127.f);
        float q1 = fminf(fmaxf(rintf(v[i].y / ws), -127.f), 127.f);
        float q2 = fminf(fmaxf(rintf(v[i].z / ws), -127.f), 127.f);
        float q3 = fminf(fmaxf(rintf(v[i].w / ws), -127.f), 127.f);
        __nv_bfloat162 p0, p1;
        p0.x = __float2bfloat16_rn(q0); p0.y = __float2bfloat16_rn(q1);
        p1.x = __float2bfloat16_rn(q2); p1.y = __float2bfloat16_rn(q3);
        *(__nv_bfloat162*)(qrow + c)     = p0;
        *(__nv_bfloat162*)(qrow + c + 2) = p1;
    }
}

// ---------------- activation quant: (clip(round(x/sc)+zp) - zp) as bf16 ----------------
__global__ void quantx_kernel(const float4* __restrict__ x4, int n4) {
    float sc = g_sc, zp = g_zp;
    __nv_bfloat162* q2 = (__nv_bfloat162*)g_qx;
    for (int i = blockIdx.x * blockDim.x + threadIdx.x; i < n4; i += gridDim.x * blockDim.x) {
        float4 v = x4[i];
        float q0 = fminf(fmaxf(rintf(v.x / sc) + zp, -128.f), 127.f) - zp;
        float q1 = fminf(fmaxf(rintf(v.y / sc) + zp, -128.f), 127.f) - zp;
        float q2v = fminf(fmaxf(rintf(v.z / sc) + zp, -128.f), 127.f) - zp;
        float q3 = fminf(fmaxf(rintf(v.w / sc) + zp, -128.f), 127.f) - zp;
        __nv_bfloat162 p0, p1;
        p0.x = __float2bfloat16_rn(q0);  p0.y = __float2bfloat16_rn(q1);
        p1.x = __float2bfloat16_rn(q2v); p1.y = __float2bfloat16_rn(q3);
        q2[2 * i]     = p0;
        q2[2 * i + 1] = p1;
    }
}

// ---------------- GEMM: bf16 mma.sync, fused qbias + res min/max epilogue ----------------
__device__ __forceinline__ void ldsm4(uint32_t& r0, uint32_t& r1, uint32_t& r2, uint32_t& r3,
                                      const __nv_bfloat16* p) {
    uint32_t addr = (uint32_t)__cvta_generic_to_shared(p);
    asm volatile("ldmatrix.sync.aligned.m8n8.x4.shared.b16 {%0,%1,%2,%3}, [%4];\n"
                 : "=r"(r0), "=r"(r1), "=r"(r2), "=r"(r3) : "r"(addr));
}

__device__ __forceinline__ void mma16816(float* d, const uint32_t* a, const uint32_t* b) {
    asm volatile(
        "mma.sync.aligned.m16n8k16.row.col.f32.bf16.bf16.f32 "
        "{%0,%1,%2,%3}, {%4,%5,%6,%7}, {%8,%9}, {%0,%1,%2,%3};\n"
        : "+f"(d[0]), "+f"(d[1]), "+f"(d[2]), "+f"(d[3])
        : "r"(a[0]), "r"(a[1]), "r"(a[2]), "r"(a[3]), "r"(b[0]), "r"(b[1]));
}

__global__ void __launch_bounds__(256, 2) gemm_kernel(const float* __restrict__ bias,
                                                      float* __restrict__ out) {
    __shared__ __nv_bfloat16 As[BM * LDSH];
    __shared__ __nv_bfloat16 Bs[BN * LDSH];
    int tid = threadIdx.x;
    int bm = blockIdx.y * BM;   // rows of x
    int bn = blockIdx.x * BN;   // output channels
    int warp = tid >> 5, lane = tid & 31;
    int wm = warp & 3, wn = warp >> 2;      // 4 x 2 warp grid
    int r = lane & 7, sub = lane >> 3;

    float acc[2][8][4];
    #pragma unroll
    for (int mi = 0; mi < 2; mi++)
        #pragma unroll
        for (int ni = 0; ni < 8; ni++)
            #pragma unroll
            for (int j = 0; j < 4; j++) acc[mi][ni][j] = 0.f;

    // ldmatrix per-lane offsets:
    // A x4 groups: [rows m..m+7 @kk], [m+8..m+15 @kk], [m..m+7 @kk+8], [m+8..m+15 @kk+8]
    int arow = r + ((sub & 1) << 3), acol = (sub >> 1) << 3;
    // B x4 groups (two n8 tiles): [n..n+7 @kk], [n..n+7 @kk+8], [n+8..n+15 @kk], [n+8..n+15 @kk+8]
    int brow = r + ((sub >> 1) << 3), bcol = (sub & 1) << 3;

    for (int k0 = 0; k0 < KDIM; k0 += BK) {
        #pragma unroll
        for (int i = 0; i < 4; i++) {
            int c = tid + i * 256;
            int rw = c >> 3, cc = (c & 7) << 3;
            *(uint4*)&As[rw * LDSH + cc] =
                *(const uint4*)&g_qx[(size_t)(bm + rw) * KDIM + k0 + cc];
            *(uint4*)&Bs[rw * LDSH + cc] =
                *(const uint4*)&g_qw[(size_t)(bn + rw) * KDIM + k0 + cc];
        }
        __syncthreads();
        #pragma unroll
        for (int kk = 0; kk < BK; kk += 16) {
            uint32_t a[2][4], b[8][2];
            #pragma unroll
            for (int mi = 0; mi < 2; mi++)
                ldsm4(a[mi][0], a[mi][1], a[mi][2], a[mi][3],
                      &As[(wm * 32 + mi * 16 + arow) * LDSH + kk + acol]);
            #pragma unroll
            for (int nj = 0; nj < 4; nj++) {
                uint32_t t0, t1, t2, t3;
                ldsm4(t0, t1, t2, t3,
                      &Bs[(wn * 64 + nj * 16 + brow) * LDSH + kk + bcol]);
                b[nj * 2][0] = t0; b[nj * 2][1] = t1;
                b[nj * 2 + 1][0] = t2; b[nj * 2 + 1][1] = t3;
            }
            #pragma unroll
            for (int mi = 0; mi < 2; mi++)
                #pragma unroll
                for (int ni = 0; ni < 8; ni++)
                    mma16816(acc[mi][ni], a[mi], b[ni]);
        }
        __syncthreads();
    }

    // epilogue: add requantized bias, track global min/max of res32, write fp32 res32
    float sc = g_sc;
    int g = lane >> 2, t = lane & 3;
    float tmx = 0.f, tmn = 0.f;
    #pragma unroll
    for (int mi = 0; mi < 2; mi++) {
        #pragma unroll
        for (int ni = 0; ni < 8; ni++) {
            int row0 = bm + wm * 32 + mi * 16 + g;
            int col0 = bn + wn * 64 + ni * 8 + 2 * t;
            float qb0 = rintf(bias[col0]     / (g_wscale[col0]     * sc));
            float qb1 = rintf(bias[col0 + 1] / (g_wscale[col0 + 1] * sc));
            float v0 = acc[mi][ni][0] + qb0;
            float v1 = acc[mi][ni][1] + qb1;
            float v2 = acc[mi][ni][2] + qb0;
            float v3 = acc[mi][ni][3] + qb1;
            tmx = fmaxf(tmx, fmaxf(fmaxf(v0, v1), fmaxf(v2, v3)));
            tmn = fminf(tmn, fminf(fminf(v0, v1), fminf(v2, v3)));
            *(float2*)&out[(size_t)row0 * ODIM + col0]       = make_float2(v0, v1);
            *(float2*)&out[(size_t)(row0 + 8) * ODIM + col0] = make_float2(v2, v3);
        }
    }
    block_minmax_atomic(tmn, tmx, &g_rmin_u, &g_rmax_u);
}

__global__ void params2_kernel() {
    float rmx = __uint_as_float(g_rmax_u);
    float rmn = __uint_as_float(g_rmin_u);
    float resc = (rmx - rmn) / 255.f;
    g_resc = resc;
    g_rezp = rintf(-128.f - rmn / resc);
}

// ---------------- in-place requant + dequant of d_out ----------------
__global__ void requant_kernel(float4* __restrict__ out4, int n4) {
    float resc = g_resc, rezp = g_rezp, sc = g_sc;
    for (int i = blockIdx.x * blockDim.x + threadIdx.x; i < n4; i += gridDim.x * blockDim.x) {
        float4 v = out4[i];
        int col = (i * 4) & (ODIM - 1);
        float s0 = (sc * g_wscale[col])     * resc;
        float s1 = (sc * g_wscale[col + 1]) * resc;
        float s2 = (sc * g_wscale[col + 2]) * resc;
        float s3 = (sc * g_wscale[col + 3]) * resc;
        float r0 = fminf(fmaxf(rintf(v.x / resc) + rezp, -128.f), 127.f);
        float r1 = fminf(fmaxf(rintf(v.y / resc) + rezp, -128.f), 127.f);
        float r2 = fminf(fmaxf(rintf(v.z / resc) + rezp, -128.f), 127.f);
        float r3 = fminf(fmaxf(rintf(v.w / resc) + rezp, -128.f), 127.f);
        v.x = (r0 - rezp) * s0;
        v.y = (r1 - rezp) * s1;
        v.z = (r2 - rezp) * s2;
        v.w = (r3 - rezp) * s3;
        out4[i] = v;
    }
}

// ---------------- launch ----------------
extern "C" void kernel_launch(void* const* d_in, const int* in_sizes, int n_in,
                              void* d_out, int out_size) {
    const float* x    = (const float*)d_in[0];
    const float* w    = (const float*)d_in[1];
    const float* bias = (const float*)d_in[2];
    float* out = (float*)d_out;

    init_kernel<<<1, 1>>>();
    minmax_x_kernel<<<2048, 256>>>((const float4*)x, NROWS * KDIM / 4);
    params1_kernel<<<1, 1>>>();
    quantw_kernel<<<ODIM, 256>>>(w);
    quantx_kernel<<<4096, 256>>>((const float4*)x, NROWS * KDIM / 4);
    dim3 grid(ODIM / BN, NROWS / BM);
    gemm_kernel<<<grid, 256>>>(bias, out);
    params2_kernel<<<1, 1>>>();
    requant_kernel<<<4096, 256>>>((float4*)out, NROWS * ODIM / 4);
}

// round 4
// speedup vs baseline: 3.1586x; 3.1586x over previous
#include <cuda_runtime.h>
#include <cuda_bf16.h>
#include <cstdint>

#define NROWS 16384
#define KDIM  4096
#define ODIM  4096

// Arch-feature guard: tcgen05 only exists in arch-specific ('a') / family targets.
#if defined(__CUDA_ARCH_FEAT_SM103_ALL) || defined(__CUDA_ARCH_FEAT_SM100_ALL) || \
    defined(__CUDA_ARCH_SPECIFIC__) || defined(__CUDA_ARCH_FAMILY_SPECIFIC__)
#define HAS_TCGEN05 1
#else
#define HAS_TCGEN05 0
#endif

// ---------------- scratch (static device globals; no allocation allowed) ----------------
__device__ __nv_bfloat16 g_qx[(size_t)NROWS * KDIM];   // 128 MB
__device__ __nv_bfloat16 g_qw[(size_t)ODIM * KDIM];    // 32 MB
__device__ float g_wscale[ODIM];
__device__ unsigned int g_xmax_u, g_xmin_u, g_rmax_u, g_rmin_u;
__device__ float g_sc, g_zp, g_resc, g_rezp;

// ---------------- PTX helpers ----------------
__device__ __forceinline__ uint32_t smem_u32(const void* p) {
    uint32_t a;
    asm("{ .reg .u64 t; cvta.to.shared.u64 t, %1; cvt.u32.u64 %0, t; }" : "=r"(a) : "l"(p));
    return a;
}
#define TCGEN05_ALLOC(sm, n) \
    asm volatile("tcgen05.alloc.cta_group::1.sync.aligned.shared::cta.b32 [%0], %1;" \
                 :: "r"((uint32_t)(sm)), "r"((uint32_t)(n)) : "memory")
#define TCGEN05_DEALLOC(t, n) \
    asm volatile("tcgen05.dealloc.cta_group::1.sync.aligned.b32 %0, %1;" :: "r"(t), "r"((uint32_t)(n)))
#define TCGEN05_RELINQ() \
    asm volatile("tcgen05.relinquish_alloc_permit.cta_group::1.sync.aligned;")
#define TCGEN05_COMMIT(mb) \
    asm volatile("tcgen05.commit.cta_group::1.mbarrier::arrive::one.shared::cluster.b64 [%0];" \
                 :: "r"((uint32_t)(mb)) : "memory")
#define TCGEN05_FENCE_AFTER()  asm volatile("tcgen05.fence::after_thread_sync;" ::: "memory")
#define TCGEN05_FENCE_BEFORE() asm volatile("tcgen05.fence::before_thread_sync;" ::: "memory")
#define TCGEN05_WAIT_LD()      asm volatile("tcgen05.wait::ld.sync.aligned;" ::: "memory")
#define MBAR_INIT(a, c) \
    asm volatile("mbarrier.init.shared.b64 [%0], %1;" :: "r"((uint32_t)(a)), "r"((uint32_t)(c)) : "memory")
#define FENCE_PROXY_ASYNC() asm volatile("fence.proxy.async.shared::cta;" ::: "memory")

#define MBAR_WAIT_PARITY(mb, par) do {                                            \
    uint32_t _m = (uint32_t)(mb); uint32_t _p = (uint32_t)(par);                  \
    asm volatile(                                                                 \
        "{\n\t.reg .pred P1;\n\t"                                                 \
        "WL_%=:\n\t"                                                              \
        "mbarrier.try_wait.parity.acquire.cta.shared::cta.b64 P1, [%0], %1, 0x989680;\n\t" \
        "@P1 bra.uni WD_%=;\n\t"                                                  \
        "bra.uni WL_%=;\n\t"                                                      \
        "WD_%=:\n\t}"                                                             \
        :: "r"(_m), "r"(_p) : "memory");                                          \
} while (0)

#define TCGEN05_LD_X32(r, addr) \
    asm volatile( \
        "tcgen05.ld.sync.aligned.32x32b.x32.b32 " \
        "{%0, %1, %2, %3, %4, %5, %6, %7, " \
        " %8, %9, %10, %11, %12, %13, %14, %15, " \
        " %16, %17, %18, %19, %20, %21, %22, %23, " \
        " %24, %25, %26, %27, %28, %29, %30, %31}, [%32];" \
        : "=r"((r)[0]),  "=r"((r)[1]),  "=r"((r)[2]),  "=r"((r)[3]), \
          "=r"((r)[4]),  "=r"((r)[5]),  "=r"((r)[6]),  "=r"((r)[7]), \
          "=r"((r)[8]),  "=r"((r)[9]),  "=r"((r)[10]), "=r"((r)[11]), \
          "=r"((r)[12]), "=r"((r)[13]), "=r"((r)[14]), "=r"((r)[15]), \
          "=r"((r)[16]), "=r"((r)[17]), "=r"((r)[18]), "=r"((r)[19]), \
          "=r"((r)[20]), "=r"((r)[21]), "=r"((r)[22]), "=r"((r)[23]), \
          "=r"((r)[24]), "=r"((r)[25]), "=r"((r)[26]), "=r"((r)[27]), \
          "=r"((r)[28]), "=r"((r)[29]), "=r"((r)[30]), "=r"((r)[31]) \
        : "r"(addr))

__device__ __forceinline__ void cp16(uint32_t s, const void* g) {
    asm volatile("cp.async.cg.shared.global [%0], [%1], 16;" :: "r"(s), "l"(g));
}
#define CP_COMMIT() asm volatile("cp.async.commit_group;" ::: "memory")
#define CP_WAIT1()  asm volatile("cp.async.wait_group 1;" ::: "memory")

// SW128 K-major bf16 descriptor (layout=2, version=1, SBO=64, LBO=1)
__device__ __forceinline__ uint64_t make_desc(uint32_t addr) {
    return ((uint64_t)2 << 61) | ((uint64_t)1 << 46) | ((uint64_t)64 << 32) |
           ((uint64_t)1 << 16) | ((addr >> 4) & 0x3FFF);
}

// idesc kind::f16: dtype=F32(bit4), atype=BF16(bit7), btype=BF16(bit10), N=256, M=128
#define GEMM_IDESC ((1u << 4) | (1u << 7) | (1u << 10) | ((256u / 8) << 17) | ((128u / 16) << 24))

__device__ __forceinline__ void mma_f16_ss(uint32_t d, uint64_t ad, uint64_t bd,
                                           uint32_t idesc, bool acc) {
    uint32_t e = acc ? 1u : 0u;
    asm volatile(
        "{\n\t.reg .pred p;\n\t"
        "setp.ne.u32 p, %4, 0;\n\t"
        "tcgen05.mma.cta_group::1.kind::f16 [%0], %1, %2, %3, {%5,%5,%5,%5}, p;\n\t"
        "}"
        :: "r"(d), "l"(ad), "l"(bd), "r"(idesc), "r"(e), "r"(0u) : "memory");
}

// ---------------- misc kernels ----------------
__global__ void init_kernel() {
    g_xmax_u = 0u; g_xmin_u = 0u; g_rmax_u = 0u; g_rmin_u = 0u;
}

__device__ __forceinline__ void block_minmax_atomic(float tmn, float tmx,
                                                    unsigned int* gmin, unsigned int* gmax) {
    #pragma unroll
    for (int o = 16; o > 0; o >>= 1) {
        tmx = fmaxf(tmx, __shfl_xor_sync(0xffffffffu, tmx, o));
        tmn = fminf(tmn, __shfl_xor_sync(0xffffffffu, tmn, o));
    }
    __shared__ float smx[32], smn[32];
    int w = threadIdx.x >> 5, nw = blockDim.x >> 5;
    if ((threadIdx.x & 31) == 0) { smx[w] = tmx; smn[w] = tmn; }
    __syncthreads();
    if (threadIdx.x == 0) {
        for (int i = 1; i < nw; i++) { tmx = fmaxf(tmx, smx[i]); tmn = fminf(tmn, smn[i]); }
        atomicMax(gmax, __float_as_uint(fmaxf(tmx, 0.f)));
        atomicMax(gmin, __float_as_uint(fminf(tmn, 0.f)));
    }
}

__global__ void minmax_x_kernel(const float4* __restrict__ x4, int n4) {
    float tmx = 0.f, tmn = 0.f;
    for (int i = blockIdx.x * blockDim.x + threadIdx.x; i < n4; i += gridDim.x * blockDim.x) {
        float4 v = x4[i];
        tmx = fmaxf(tmx, fmaxf(fmaxf(v.x, v.y), fmaxf(v.z, v.w)));
        tmn = fminf(tmn, fminf(fminf(v.x, v.y), fminf(v.z, v.w)));
    }
    block_minmax_atomic(tmn, tmx, &g_xmin_u, &g_xmax_u);
}

__global__ void params1_kernel() {
    float mx = __uint_as_float(g_xmax_u);
    float mn = __uint_as_float(g_xmin_u);
    float sc = (mx - mn) / 255.f;
    g_sc = sc;
    g_zp = rintf(-128.f - mn / sc);
}

__global__ void quantw_kernel(const float* __restrict__ w) {
    int row = blockIdx.x;
    const float4* wr = (const float4*)(w + (size_t)row * KDIM);
    float4 v[4];
    float am = 0.f;
    #pragma unroll
    for (int i = 0; i < 4; i++) {
        v[i] = wr[threadIdx.x + i * 256];
        am = fmaxf(am, fmaxf(fmaxf(fabsf(v[i].x), fabsf(v[i].y)),
                             fmaxf(fabsf(v[i].z), fabsf(v[i].w))));
    }
    #pragma unroll
    for (int o = 16; o > 0; o >>= 1) am = fmaxf(am, __shfl_xor_sync(0xffffffffu, am, o));
    __shared__ float sred[8];
    __shared__ float swsv;
    if ((threadIdx.x & 31) == 0) sred[threadIdx.x >> 5] = am;
    __syncthreads();
    if (threadIdx.x == 0) {
        for (int i = 1; i < 8; i++) am = fmaxf(am, sred[i]);
        float ws = am / 127.f;
        swsv = ws;
        g_wscale[row] = ws;
    }
    __syncthreads();
    float ws = swsv;
    __nv_bfloat16* qrow = g_qw + (size_t)row * KDIM;
    #pragma unroll
    for (int i = 0; i < 4; i++) {
        int c = (threadIdx.x + i * 256) * 4;
        float q0 = fminf(fmaxf(rintf(v[i].x / ws), -127.f), 127.f);
        float q1 = fminf(fmaxf(rintf(v[i].y / ws), -127.f), 127.f);
        float q2 = fminf(fmaxf(rintf(v[i].z / ws), -127.f), 127.f);
        float q3 = fminf(fmaxf(rintf(v[i].w / ws), -127.f), 127.f);
        __nv_bfloat162 p0, p1;
        p0.x = __float2bfloat16_rn(q0); p0.y = __float2bfloat16_rn(q1);
        p1.x = __float2bfloat16_rn(q2); p1.y = __float2bfloat16_rn(q3);
        *(__nv_bfloat162*)(qrow + c)     = p0;
        *(__nv_bfloat162*)(qrow + c + 2) = p1;
    }
}

__global__ void quantx_kernel(const float4* __restrict__ x4, int n4) {
    float sc = g_sc, zp = g_zp;
    __nv_bfloat162* q2 = (__nv_bfloat162*)g_qx;
    for (int i = blockIdx.x * blockDim.x + threadIdx.x; i < n4; i += gridDim.x * blockDim.x) {
        float4 v = x4[i];
        float q0 = fminf(fmaxf(rintf(v.x / sc) + zp, -128.f), 127.f) - zp;
        float q1 = fminf(fmaxf(rintf(v.y / sc) + zp, -128.f), 127.f) - zp;
        float q2v = fminf(fmaxf(rintf(v.z / sc) + zp, -128.f), 127.f) - zp;
        float q3 = fminf(fmaxf(rintf(v.w / sc) + zp, -128.f), 127.f) - zp;
        __nv_bfloat162 p0, p1;
        p0.x = __float2bfloat16_rn(q0);  p0.y = __float2bfloat16_rn(q1);
        p1.x = __float2bfloat16_rn(q2v); p1.y = __float2bfloat16_rn(q3);
        q2[2 * i]     = p0;
        q2[2 * i + 1] = p1;
    }
}

// ================= tcgen05 GEMM (sm_103a path): 256x256 tile, BK=64, 3 stages =================
#define STAGES 3
#define STAGE_BYTES 65536
#define SMEM_STAGE0 1024
#define SMEM_QB (SMEM_STAGE0 + STAGES * STAGE_BYTES)
#define GEMM_SMEM (SMEM_QB + 256 * 4)
#define NKITER (KDIM / 64)

#if HAS_TCGEN05
__device__ __forceinline__ void load_stage(uint32_t sbase, int k0, int bm, int bn, int tid) {
    const char* Ag = (const char*)(g_qx + (size_t)bm * KDIM + k0 * 64);
    const char* Bg = (const char*)(g_qw + (size_t)bn * KDIM + k0 * 64);
    #pragma unroll
    for (int i = 0; i < 8; i++) {
        int c = tid + i * 256;                 // 0..2047 16B-chunk id
        int row = c >> 3, cc = c & 7;
        uint32_t sw = (uint32_t)(row * 128) + (uint32_t)((cc ^ (row & 7)) << 4);
        cp16(sbase + sw,         Ag + (size_t)row * (KDIM * 2) + cc * 16);
        cp16(sbase + 32768 + sw, Bg + (size_t)row * (KDIM * 2) + cc * 16);
    }
}
#endif

__global__ void __launch_bounds__(256, 1) gemm_tc_kernel(const float* __restrict__ bias,
                                                         float* __restrict__ out) {
#if HAS_TCGEN05
    extern __shared__ __align__(1024) char ds[];
    uint32_t sb = smem_u32(ds);
    int tid = threadIdx.x, wid = tid >> 5, lane = tid & 31;
    int bm = blockIdx.y * 256, bn = blockIdx.x * 256;

    if (wid == 0) TCGEN05_ALLOC(sb + 0, 512);
    if (tid == 0) {
        #pragma unroll
        for (int s = 0; s < STAGES; s++) MBAR_INIT(sb + 8 + s * 8, 1);
    }
    __syncthreads();
    uint32_t tb;
    asm volatile("ld.shared.b32 %0, [%1];" : "=r"(tb) : "r"(sb));

    load_stage(sb + SMEM_STAGE0 + 0 * STAGE_BYTES, 0, bm, bn, tid); CP_COMMIT();
    load_stage(sb + SMEM_STAGE0 + 1 * STAGE_BYTES, 1, bm, bn, tid); CP_COMMIT();

    int ph0 = 0, ph1 = 0, ph2 = 0;
    for (int k0 = 0; k0 < NKITER; k0++) {
        int s = k0 % STAGES;
        CP_WAIT1();
        FENCE_PROXY_ASYNC();
        __syncthreads();

        if (tid == 0) {
            uint32_t stg = sb + SMEM_STAGE0 + s * STAGE_BYTES;
            uint64_t ab = make_desc(stg);
            uint64_t bb = make_desc(stg + 32768);
            #pragma unroll
            for (int atom = 0; atom < 2; atom++)
                #pragma unroll
                for (int kk = 0; kk < 4; kk++)
                    mma_f16_ss(tb + atom * 256, ab + atom * 1024 + kk * 2, bb + kk * 2,
                               GEMM_IDESC, !(k0 == 0 && kk == 0));
            TCGEN05_COMMIT(sb + 8 + s * 8);
        }

        int kl = k0 + STAGES - 1;
        if (kl < NKITER) {
            int t = kl % STAGES;
            if (k0 > 0) {                      // WAR: slot reused, wait MMA of iter k0-1
                int ph = (t == 0) ? ph0 : (t == 1) ? ph1 : ph2;
                MBAR_WAIT_PARITY(sb + 8 + t * 8, ph);
                if (t == 0) ph0 ^= 1; else if (t == 1) ph1 ^= 1; else ph2 ^= 1;
            }
            load_stage(sb + SMEM_STAGE0 + t * STAGE_BYTES, kl, bm, bn, tid);
        }
        CP_COMMIT();
    }

    {
        int sl = (NKITER - 1) % STAGES;
        int ph = (sl == 0) ? ph0 : (sl == 1) ? ph1 : ph2;
        MBAR_WAIT_PARITY(sb + 8 + sl * 8, ph);
    }
    TCGEN05_FENCE_AFTER();

    float sc = g_sc;
    float* qb = (float*)(ds + SMEM_QB);
    {
        int col = bn + tid;
        qb[tid] = rintf(bias[col] / (g_wscale[col] * sc));
    }
    __syncthreads();

    int atom = wid >> 2;
    int row = bm + atom * 128 + (wid & 3) * 32 + lane;
    float tmx = 0.f, tmn = 0.f;
    float* orow = out + (size_t)row * ODIM + bn;
    #pragma unroll
    for (int ch = 0; ch < 8; ch++) {
        uint32_t dr[32];
        TCGEN05_LD_X32(dr, tb + atom * 256 + ch * 32);
        TCGEN05_WAIT_LD();
        float v[32];
        #pragma unroll
        for (int c = 0; c < 32; c++) {
            float f = __uint_as_float(dr[c]) + qb[ch * 32 + c];
            v[c] = f;
            tmx = fmaxf(tmx, f);
            tmn = fminf(tmn, f);
        }
        #pragma unroll
        for (int c = 0; c < 32; c += 4)
            *(float4*)&orow[ch * 32 + c] = make_float4(v[c], v[c + 1], v[c + 2], v[c + 3]);
    }
    TCGEN05_FENCE_BEFORE();
    block_minmax_atomic(tmn, tmx, &g_rmin_u, &g_rmax_u);
    __syncthreads();
    if (wid == 0) {
        TCGEN05_RELINQ();
        TCGEN05_DEALLOC(tb, 512);
    }
#endif
}

// ================= HMMA fallback GEMM (plain sm_103 path): round-2 kernel =================
#define BM 128
#define BN 128
#define BK 64
#define LDSH (BK + 8)

#if !HAS_TCGEN05
__device__ __forceinline__ void ldsm4(uint32_t& r0, uint32_t& r1, uint32_t& r2, uint32_t& r3,
                                      const __nv_bfloat16* p) {
    uint32_t addr = (uint32_t)__cvta_generic_to_shared(p);
    asm volatile("ldmatrix.sync.aligned.m8n8.x4.shared.b16 {%0,%1,%2,%3}, [%4];\n"
                 : "=r"(r0), "=r"(r1), "=r"(r2), "=r"(r3) : "r"(addr));
}
__device__ __forceinline__ void mma16816(float* d, const uint32_t* a, const uint32_t* b) {
    asm volatile(
        "mma.sync.aligned.m16n8k16.row.col.f32.bf16.bf16.f32 "
        "{%0,%1,%2,%3}, {%4,%5,%6,%7}, {%8,%9}, {%0,%1,%2,%3};\n"
        : "+f"(d[0]), "+f"(d[1]), "+f"(d[2]), "+f"(d[3])
        : "r"(a[0]), "r"(a[1]), "r"(a[2]), "r"(a[3]), "r"(b[0]), "r"(b[1]));
}
#endif

__global__ void __launch_bounds__(256, 2) gemm_hmma_kernel(const float* __restrict__ bias,
                                                           float* __restrict__ out) {
#if !HAS_TCGEN05
    __shared__ __nv_bfloat16 As[BM * LDSH];
    __shared__ __nv_bfloat16 Bs[BN * LDSH];
    int tid = threadIdx.x;
    int bm = blockIdx.y * BM;
    int bn = blockIdx.x * BN;
    int warp = tid >> 5, lane = tid & 31;
    int wm = warp & 3, wn = warp >> 2;
    int r = lane & 7, sub = lane >> 3;

    float acc[2][8][4];
    #pragma unroll
    for (int mi = 0; mi < 2; mi++)
        #pragma unroll
        for (int ni = 0; ni < 8; ni++)
            #pragma unroll
            for (int j = 0; j < 4; j++) acc[mi][ni][j] = 0.f;

    int arow = r + ((sub & 1) << 3), acol = (sub >> 1) << 3;
    int brow = r + ((sub >> 1) << 3), bcol = (sub & 1) << 3;

    for (int k0 = 0; k0 < KDIM; k0 += BK) {
        #pragma unroll
        for (int i = 0; i < 4; i++) {
            int c = tid + i * 256;
            int rw = c >> 3, cc = (c & 7) << 3;
            *(uint4*)&As[rw * LDSH + cc] =
                *(const uint4*)&g_qx[(size_t)(bm + rw) * KDIM + k0 + cc];
            *(uint4*)&Bs[rw * LDSH + cc] =
                *(const uint4*)&g_qw[(size_t)(bn + rw) * KDIM + k0 + cc];
        }
        __syncthreads();
        #pragma unroll
        for (int kk = 0; kk < BK; kk += 16) {
            uint32_t a[2][4], b[8][2];
            #pragma unroll
            for (int mi = 0; mi < 2; mi++)
                ldsm4(a[mi][0], a[mi][1], a[mi][2], a[mi][3],
                      &As[(wm * 32 + mi * 16 + arow) * LDSH + kk + acol]);
            #pragma unroll
            for (int nj = 0; nj < 4; nj++) {
                uint32_t t0, t1, t2, t3;
                ldsm4(t0, t1, t2, t3,
                      &Bs[(wn * 64 + nj * 16 + brow) * LDSH + kk + bcol]);
                b[nj * 2][0] = t0; b[nj * 2][1] = t1;
                b[nj * 2 + 1][0] = t2; b[nj * 2 + 1][1] = t3;
            }
            #pragma unroll
            for (int mi = 0; mi < 2; mi++)
                #pragma unroll
                for (int ni = 0; ni < 8; ni++)
                    mma16816(acc[mi][ni], a[mi], b[ni]);
        }
        __syncthreads();
    }

    float sc = g_sc;
    int g = lane >> 2, t = lane & 3;
    float tmx = 0.f, tmn = 0.f;
    #pragma unroll
    for (int mi = 0; mi < 2; mi++) {
        #pragma unroll
        for (int ni = 0; ni < 8; ni++) {
            int row0 = bm + wm * 32 + mi * 16 + g;
            int col0 = bn + wn * 64 + ni * 8 + 2 * t;
            float qb0 = rintf(bias[col0]     / (g_wscale[col0]     * sc));
            float qb1 = rintf(bias[col0 + 1] / (g_wscale[col0 + 1] * sc));
            float v0 = acc[mi][ni][0] + qb0;
            float v1 = acc[mi][ni][1] + qb1;
            float v2 = acc[mi][ni][2] + qb0;
            float v3 = acc[mi][ni][3] + qb1;
            tmx = fmaxf(tmx, fmaxf(fmaxf(v0, v1), fmaxf(v2, v3)));
            tmn = fminf(tmn, fminf(fminf(v0, v1), fminf(v2, v3)));
            *(float2*)&out[(size_t)row0 * ODIM + col0]       = make_float2(v0, v1);
            *(float2*)&out[(size_t)(row0 + 8) * ODIM + col0] = make_float2(v2, v3);
        }
    }
    block_minmax_atomic(tmn, tmx, &g_rmin_u, &g_rmax_u);
#endif
}

__global__ void params2_kernel() {
    float rmx = __uint_as_float(g_rmax_u);
    float rmn = __uint_as_float(g_rmin_u);
    float resc = (rmx - rmn) / 255.f;
    g_resc = resc;
    g_rezp = rintf(-128.f - rmn / resc);
}

__global__ void requant_kernel(float4* __restrict__ out4, int n4) {
    float resc = g_resc, rezp = g_rezp, sc = g_sc;
    for (int i = blockIdx.x * blockDim.x + threadIdx.x; i < n4; i += gridDim.x * blockDim.x) {
        float4 v = out4[i];
        int col = (i * 4) & (ODIM - 1);
        float s0 = (sc * g_wscale[col])     * resc;
        float s1 = (sc * g_wscale[col + 1]) * resc;
        float s2 = (sc * g_wscale[col + 2]) * resc;
        float s3 = (sc * g_wscale[col + 3]) * resc;
        float r0 = fminf(fmaxf(rintf(v.x / resc) + rezp, -128.f), 127.f);
        float r1 = fminf(fmaxf(rintf(v.y / resc) + rezp, -128.f), 127.f);
        float r2 = fminf(fmaxf(rintf(v.z / resc) + rezp, -128.f), 127.f);
        float r3 = fminf(fmaxf(rintf(v.w / resc) + rezp, -128.f), 127.f);
        v.x = (r0 - rezp) * s0;
        v.y = (r1 - rezp) * s1;
        v.z = (r2 - rezp) * s2;
        v.w = (r3 - rezp) * s3;
        out4[i] = v;
    }
}

// ---------------- launch ----------------
extern "C" void kernel_launch(void* const* d_in, const int* in_sizes, int n_in,
                              void* d_out, int out_size) {
    const float* x    = (const float*)d_in[0];
    const float* w    = (const float*)d_in[1];
    const float* bias = (const float*)d_in[2];
    float* out = (float*)d_out;

    cudaFuncSetAttribute(gemm_tc_kernel, cudaFuncAttributeMaxDynamicSharedMemorySize, GEMM_SMEM);

    init_kernel<<<1, 1>>>();
    minmax_x_kernel<<<2048, 256>>>((const float4*)x, NROWS * KDIM / 4);
    params1_kernel<<<1, 1>>>();
    quantw_kernel<<<ODIM, 256>>>(w);
    quantx_kernel<<<4096, 256>>>((const float4*)x, NROWS * KDIM / 4);

    // Exactly one of these two has a compiled body in the cubin the driver loads.
    dim3 grid_tc(ODIM / 256, NROWS / 256);
    gemm_tc_kernel<<<grid_tc, 256, GEMM_SMEM>>>(bias, out);
    dim3 grid_hm(ODIM / BN, NROWS / BM);
    gemm_hmma_kernel<<<grid_hm, 256>>>(bias, out);

    params2_kernel<<<1, 1>>>();
    requant_kernel<<<4096, 256>>>((float4*)out, NROWS * ODIM / 4);
}